// round 9
// baseline (speedup 1.0000x reference)
#include <cuda_runtime.h>
#include <cuda_bf16.h>
#include <cuda_fp16.h>
#include <cstdint>

#define N_TOK  8192
#define DMODEL 1024
#define NE     8
#define CAP    0.8f

#define TM 128
#define TN 128
#define KC 64
#define NCHUNK (DMODEL / KC)   // 16
#define STAGES 3

// ---------------- device scratch (allocation-free rule) ----------------
__device__ int   g_count[NE];
__device__ int   g_list[NE * N_TOK];
__device__ float g_wt  [NE * N_TOK];
__device__ __half g_xh[(size_t)N_TOK * DMODEL];
__device__ __half g_w1h[(size_t)NE * DMODEL * DMODEL];
__device__ __half g_w2h[(size_t)NE * DMODEL * DMODEL];
__device__ __half g_h  [(size_t)NE * N_TOK * DMODEL];

// ---------------- helpers ----------------
__device__ __forceinline__ uint32_t smem_u32(const void* p) {
    uint32_t a;
    asm("{ .reg .u64 t; cvta.to.shared.u64 t, %1; cvt.u32.u64 %0, t; }" : "=r"(a) : "l"(p));
    return a;
}
// SW64 swizzle for 64-byte rows (8 rows x 64B atom)
__device__ __forceinline__ uint32_t sw64(uint32_t off) { return off ^ ((off >> 3) & 0x30); }

#define CP16(dst, src) \
    asm volatile("cp.async.cg.shared.global [%0], [%1], 16;" :: "r"(dst), "l"(src) : "memory")
#define CP_COMMIT() asm volatile("cp.async.commit_group;" ::: "memory")
#define CP_WAIT1()  asm volatile("cp.async.wait_group 1;" ::: "memory")

__device__ __forceinline__ void ldsm4(uint32_t (&r)[4], uint32_t addr) {
    asm volatile("ldmatrix.sync.aligned.m8n8.x4.shared.b16 {%0,%1,%2,%3}, [%4];"
                 : "=r"(r[0]), "=r"(r[1]), "=r"(r[2]), "=r"(r[3]) : "r"(addr));
}
__device__ __forceinline__ void mma16816(float* d, const uint32_t* a, uint32_t b0, uint32_t b1) {
    asm volatile(
        "mma.sync.aligned.m16n8k16.row.col.f32.f16.f16.f32 "
        "{%0,%1,%2,%3}, {%4,%5,%6,%7}, {%8,%9}, {%0,%1,%2,%3};"
        : "+f"(d[0]), "+f"(d[1]), "+f"(d[2]), "+f"(d[3])
        : "r"(a[0]), "r"(a[1]), "r"(a[2]), "r"(a[3]), "r"(b0), "r"(b1));
}

// ---------------- routing (also converts x -> fp16) ----------------
__global__ void zero_counts_kernel() {
    if (threadIdx.x < NE) g_count[threadIdx.x] = 0;
}

__global__ void router_kernel(const float* __restrict__ x,
                              const float* __restrict__ Wsel,
                              const float* __restrict__ bsel) {
    int warp = threadIdx.x >> 5;
    int lane = threadIdx.x & 31;
    int n = blockIdx.x * 8 + warp;
    if (n >= N_TOK) return;

    const float* xr = x + (size_t)n * DMODEL;
    __half* xo = g_xh + (size_t)n * DMODEL;
    float acc[NE];
#pragma unroll
    for (int e = 0; e < NE; e++) acc[e] = 0.f;
    for (int d = lane; d < DMODEL; d += 32) {
        float xv = xr[d];
        xo[d] = __float2half(xv);          // fused fp16 convert
        const float4* w4 = reinterpret_cast<const float4*>(Wsel + (size_t)d * NE);
        float4 wa = w4[0], wb = w4[1];
        acc[0] += xv * wa.x; acc[1] += xv * wa.y; acc[2] += xv * wa.z; acc[3] += xv * wa.w;
        acc[4] += xv * wb.x; acc[5] += xv * wb.y; acc[6] += xv * wb.z; acc[7] += xv * wb.w;
    }
#pragma unroll
    for (int off = 16; off; off >>= 1)
#pragma unroll
        for (int e = 0; e < NE; e++) acc[e] += __shfl_xor_sync(0xffffffffu, acc[e], off);

    if (lane == 0) {
        float w[NE];
        float mx = -1e30f;
#pragma unroll
        for (int e = 0; e < NE; e++) { w[e] = acc[e] + bsel[e]; mx = fmaxf(mx, w[e]); }
        float s = 0.f;
#pragma unroll
        for (int e = 0; e < NE; e++) { w[e] = expf(w[e] - mx); s += w[e]; }
        float inv = 1.f / s;
#pragma unroll
        for (int e = 0; e < NE; e++) w[e] *= inv;

        int ord[NE]; bool used[NE];
#pragma unroll
        for (int e = 0; e < NE; e++) used[e] = false;
#pragma unroll
        for (int j = 0; j < NE; j++) {
            int best = -1; float bv = -1e30f;
#pragma unroll
            for (int e = 0; e < NE; e++)
                if (!used[e] && w[e] > bv) { bv = w[e]; best = e; }
            ord[j] = best; used[best] = true;
        }
        float sws[NE]; float cum = 0.f;
#pragma unroll
        for (int j = 0; j < NE; j++) {
            float tw = w[ord[j]];
            cum += tw;
            sws[j] = fmaxf(fminf(cum, CAP) - cum + tw, 0.f);
        }
#pragma unroll
        for (int e = 0; e < NE; e++) {
            float wt = sws[ord[e]];   // faithful take_along_axis(sw_sorted, order)
            if (wt > 0.f) {
                int pos = atomicAdd(&g_count[e], 1);
                g_list[e * N_TOK + pos] = n;
                g_wt [e * N_TOK + pos] = wt;
            }
        }
    }
}

// ---------------- prep: transpose W1 & W2 -> [e][n][k] fp16 (one launch) ----------------
__global__ void transpose_all_kernel(const float* __restrict__ W1,
                                     const float* __restrict__ W2) {
    int z = blockIdx.z;
    int e = z & 7;
    const float* W = (z < 8) ? W1 : W2;
    __half* Th = (z < 8) ? g_w1h : g_w2h;
    int k0 = blockIdx.x * 32;
    int n0 = blockIdx.y * 32;
    __shared__ float t[32][33];
    int tx = threadIdx.x, ty = threadIdx.y;   // (32,8)
    const float* src = W + ((size_t)e * DMODEL + k0) * DMODEL + n0;
#pragma unroll
    for (int j = 0; j < 4; j++)
        t[ty + 8 * j][tx] = src[(size_t)(ty + 8 * j) * DMODEL + tx];
    __syncthreads();
    size_t obase = (size_t)e * DMODEL * DMODEL;
#pragma unroll
    for (int j = 0; j < 4; j++) {
        float v = t[tx][ty + 8 * j];
        size_t o = obase + (size_t)(n0 + ty + 8 * j) * DMODEL + k0 + tx;
        Th[o] = __float2half(v);
    }
}

// ---------------- HMMA expert GEMM ----------------
// 128x128 CTA tile, 8 warps (2 M x 4 N), 64x32 per warp, single fp16 A & B.
// KC=64 staged as two 32-k halves with 64B rows:
// stage = [A half0 8K][A half1 8K][B half0 8K][B half1 8K] = 32KB; 3 stages = 96KB.
#define HALF_B  8192
#define STAGE_BYTES (4 * HALF_B)           // 32KB
#define SMEM_BYTES  (STAGES * STAGE_BYTES) // 96KB

template<int PHASE>
__global__ __launch_bounds__(256, 2)
void moe_gemm(const float* __restrict__ bias, float* __restrict__ out) {
    int e = blockIdx.z;
    int cnt = g_count[e];
    int row0 = blockIdx.x * TM;
    if (row0 >= cnt) return;
    int n0 = blockIdx.y * TN;

    extern __shared__ char smem[];
    uint32_t sbase = smem_u32(smem);

    int tid = threadIdx.x, wid = tid >> 5, lane = tid & 31;

    // ---- loader setup: thread covers rows {tid>>2, (tid>>2)+64}, segment tid&3 ----
    int seg = tid & 3;                 // 16B segment within 64B row
    int r0l = tid >> 2;                // 0..63
    const __half *ahr[2], *bhr[2];
    uint32_t sts_off[2];
#pragma unroll
    for (int i = 0; i < 2; i++) {
        int rl = r0l + 64 * i;         // 0..127 within tile
        int r = row0 + rl; if (r > cnt - 1) r = cnt - 1;
        if (PHASE == 1) {
            ahr[i] = g_xh + (size_t)g_list[e * N_TOK + r] * DMODEL;
        } else {
            ahr[i] = g_h + ((size_t)e * N_TOK + r) * DMODEL;
        }
        size_t brow = ((size_t)e * DMODEL + (n0 + rl)) * DMODEL;
        bhr[i] = ((PHASE == 1) ? g_w1h : g_w2h) + brow;
        sts_off[i] = sw64((uint32_t)rl * 64 + seg * 16);
    }

    auto load_stage = [&](int s, int c) {
        uint32_t st = sbase + s * STAGE_BYTES;
        int k0 = c * KC + seg * 8;
#pragma unroll
        for (int i = 0; i < 2; i++) {
            CP16(st + 0 * HALF_B + sts_off[i], (const void*)(ahr[i] + k0));
            CP16(st + 1 * HALF_B + sts_off[i], (const void*)(ahr[i] + k0 + 32));
            CP16(st + 2 * HALF_B + sts_off[i], (const void*)(bhr[i] + k0));
            CP16(st + 3 * HALF_B + sts_off[i], (const void*)(bhr[i] + k0 + 32));
        }
    };

    // ---- compute setup ----
    int warpM = wid & 1;       // 0..1
    int warpN = wid >> 1;      // 0..3
    int a_row = (lane & 15);
    int kchunk16 = (lane >> 4) * 16;     // 0 or 16 bytes
    int b_row = (lane & 7) + ((lane >> 3) & 1) * 8;

    uint32_t arowb[4], browb[2];
#pragma unroll
    for (int mt = 0; mt < 4; mt++)
        arowb[mt] = (uint32_t)(warpM * 64 + mt * 16 + a_row) * 64;
#pragma unroll
    for (int g = 0; g < 2; g++)
        browb[g] = (uint32_t)(warpN * 32 + g * 16 + b_row) * 64;

    float acc[4][4][4];
#pragma unroll
    for (int mt = 0; mt < 4; mt++)
#pragma unroll
        for (int j = 0; j < 4; j++)
#pragma unroll
            for (int q = 0; q < 4; q++) acc[mt][j][q] = 0.f;

    // ---- pipeline: 3 stages, depth-2 prologue, 1 barrier per chunk ----
    load_stage(0, 0); CP_COMMIT();
    load_stage(1, 1); CP_COMMIT();

    int s = 0;
    for (int c = 0; c < NCHUNK; ++c) {
        CP_WAIT1();
        __syncthreads();

        uint32_t st = sbase + s * STAGE_BYTES;

#pragma unroll
        for (int k16 = 0; k16 < KC / 16; ++k16) {
            uint32_t half_off = (uint32_t)(k16 >> 1) * HALF_B;
            uint32_t sA = st + half_off;
            uint32_t sB = st + 2 * HALF_B + half_off;
            uint32_t koff = (uint32_t)(k16 & 1) * 32 + kchunk16;
            uint32_t bf[2][4];
#pragma unroll
            for (int g = 0; g < 2; g++) {
                uint32_t so = sw64(browb[g] + koff);
                ldsm4(bf[g], sB + so);
            }
#pragma unroll
            for (int mt = 0; mt < 4; mt++) {
                uint32_t af[4];
                uint32_t so = sw64(arowb[mt] + koff);
                ldsm4(af, sA + so);
#pragma unroll
                for (int j = 0; j < 4; j++) {
                    int g = j >> 1, sub = j & 1;
                    mma16816(acc[mt][j], af, bf[g][0 + sub], bf[g][2 + sub]);
                }
            }
        }
        if (c + 2 < NCHUNK) load_stage((c + 2) % STAGES, c + 2);
        CP_COMMIT();
        if (++s == STAGES) s = 0;
    }

    // ---- epilogue ----
    int mrow_base = row0 + warpM * 64 + (lane >> 2);
    int ncol_base = n0 + warpN * 32 + (lane & 3) * 2;

    if (PHASE == 1) {
#pragma unroll
        for (int mt = 0; mt < 4; mt++) {
#pragma unroll
            for (int half = 0; half < 2; half++) {
                int r = mrow_base + mt * 16 + half * 8;
                if (r >= cnt) continue;
                size_t hb = ((size_t)e * N_TOK + r) * DMODEL;
#pragma unroll
                for (int j = 0; j < 4; j++) {
                    int ncol = ncol_base + j * 8;
                    float v0 = acc[mt][j][half * 2 + 0] + bias[e * DMODEL + ncol];
                    float v1 = acc[mt][j][half * 2 + 1] + bias[e * DMODEL + ncol + 1];
                    v0 = fmaxf(v0, 0.f); v1 = fmaxf(v1, 0.f);
                    __half2 hp;
                    hp.x = __float2half(v0); hp.y = __float2half(v1);
                    *reinterpret_cast<__half2*>(&g_h[hb + ncol]) = hp;
                }
            }
        }
    } else {
#pragma unroll
        for (int mt = 0; mt < 4; mt++) {
#pragma unroll
            for (int half = 0; half < 2; half++) {
                int r = mrow_base + mt * 16 + half * 8;
                if (r >= cnt) continue;
                int tok = g_list[e * N_TOK + r];
                float wt = g_wt[e * N_TOK + r];
                float* orow = out + (size_t)tok * DMODEL;
#pragma unroll
                for (int j = 0; j < 4; j++) {
                    int ncol = ncol_base + j * 8;
                    float y0 = acc[mt][j][half * 2 + 0] + bias[e * DMODEL + ncol];
                    float y1 = acc[mt][j][half * 2 + 1] + bias[e * DMODEL + ncol + 1];
                    atomicAdd(orow + ncol,     wt * y0);
                    atomicAdd(orow + ncol + 1, wt * y1);
                }
            }
        }
    }
}

// ---------------- launch ----------------
extern "C" void kernel_launch(void* const* d_in, const int* in_sizes, int n_in,
                              void* d_out, int out_size) {
    const float* x    = (const float*)d_in[0];
    const float* Wsel = (const float*)d_in[1];
    const float* bsel = (const float*)d_in[2];
    const float* W1   = (const float*)d_in[3];
    const float* b1   = (const float*)d_in[4];
    const float* W2   = (const float*)d_in[5];
    const float* b2   = (const float*)d_in[6];
    float* out = (float*)d_out;

    cudaFuncSetAttribute(moe_gemm<1>, cudaFuncAttributeMaxDynamicSharedMemorySize, SMEM_BYTES);
    cudaFuncSetAttribute(moe_gemm<2>, cudaFuncAttributeMaxDynamicSharedMemorySize, SMEM_BYTES);

    cudaMemsetAsync(out, 0, (size_t)out_size * sizeof(float));
    zero_counts_kernel<<<1, 32>>>();
    router_kernel<<<N_TOK / 8, 256>>>(x, Wsel, bsel);
    {
        dim3 g(32, 32, 16), b(32, 8);
        transpose_all_kernel<<<g, b>>>(W1, W2);
    }

    dim3 gg(N_TOK / TM, DMODEL / TN, NE);
    moe_gemm<1><<<gg, 256, SMEM_BYTES>>>(b1, nullptr);
    moe_gemm<2><<<gg, 256, SMEM_BYTES>>>(b2, out);
}

// round 10
// speedup vs baseline: 1.1035x; 1.1035x over previous
#include <cuda_runtime.h>
#include <cuda_bf16.h>
#include <cuda_fp16.h>
#include <cstdint>

#define N_TOK  8192
#define DMODEL 1024
#define NE     8
#define CAP    0.8f

#define TM 128
#define TN 64
#define KC 32
#define NCHUNK (DMODEL / KC)   // 32
#define STAGES 4

// ---------------- device scratch (allocation-free rule) ----------------
__device__ int   g_count[NE];
__device__ int   g_list[NE * N_TOK];
__device__ float g_wt  [NE * N_TOK];
__device__ __half g_xh[(size_t)N_TOK * DMODEL];
__device__ __half g_w1h[(size_t)NE * DMODEL * DMODEL];
__device__ __half g_w2h[(size_t)NE * DMODEL * DMODEL];
__device__ __half g_h  [(size_t)NE * N_TOK * DMODEL];

// ---------------- helpers ----------------
__device__ __forceinline__ uint32_t smem_u32(const void* p) {
    uint32_t a;
    asm("{ .reg .u64 t; cvta.to.shared.u64 t, %1; cvt.u32.u64 %0, t; }" : "=r"(a) : "l"(p));
    return a;
}
// SW64 swizzle for 64-byte rows (8 rows x 64B atom)
__device__ __forceinline__ uint32_t sw64(uint32_t off) { return off ^ ((off >> 3) & 0x30); }

#define CP16(dst, src) \
    asm volatile("cp.async.cg.shared.global [%0], [%1], 16;" :: "r"(dst), "l"(src) : "memory")
#define CP_COMMIT() asm volatile("cp.async.commit_group;" ::: "memory")
#define CP_WAIT2()  asm volatile("cp.async.wait_group 2;" ::: "memory")

__device__ __forceinline__ void ldsm4(uint32_t (&r)[4], uint32_t addr) {
    asm volatile("ldmatrix.sync.aligned.m8n8.x4.shared.b16 {%0,%1,%2,%3}, [%4];"
                 : "=r"(r[0]), "=r"(r[1]), "=r"(r[2]), "=r"(r[3]) : "r"(addr));
}
__device__ __forceinline__ void mma16816(float* d, const uint32_t* a, uint32_t b0, uint32_t b1) {
    asm volatile(
        "mma.sync.aligned.m16n8k16.row.col.f32.f16.f16.f32 "
        "{%0,%1,%2,%3}, {%4,%5,%6,%7}, {%8,%9}, {%0,%1,%2,%3};"
        : "+f"(d[0]), "+f"(d[1]), "+f"(d[2]), "+f"(d[3])
        : "r"(a[0]), "r"(a[1]), "r"(a[2]), "r"(a[3]), "r"(b0), "r"(b1));
}

// ---------------- routing ----------------
__global__ void zero_counts_kernel() {
    if (threadIdx.x < NE) g_count[threadIdx.x] = 0;
}

__global__ void router_kernel(const float* __restrict__ x,
                              const float* __restrict__ Wsel,
                              const float* __restrict__ bsel) {
    int warp = threadIdx.x >> 5;
    int lane = threadIdx.x & 31;
    int n = blockIdx.x * 8 + warp;
    if (n >= N_TOK) return;

    const float* xr = x + (size_t)n * DMODEL;
    float acc[NE];
#pragma unroll
    for (int e = 0; e < NE; e++) acc[e] = 0.f;
    for (int d = lane; d < DMODEL; d += 32) {
        float xv = xr[d];
        const float4* w4 = reinterpret_cast<const float4*>(Wsel + (size_t)d * NE);
        float4 wa = w4[0], wb = w4[1];
        acc[0] += xv * wa.x; acc[1] += xv * wa.y; acc[2] += xv * wa.z; acc[3] += xv * wa.w;
        acc[4] += xv * wb.x; acc[5] += xv * wb.y; acc[6] += xv * wb.z; acc[7] += xv * wb.w;
    }
#pragma unroll
    for (int off = 16; off; off >>= 1)
#pragma unroll
        for (int e = 0; e < NE; e++) acc[e] += __shfl_xor_sync(0xffffffffu, acc[e], off);

    if (lane == 0) {
        float w[NE];
        float mx = -1e30f;
#pragma unroll
        for (int e = 0; e < NE; e++) { w[e] = acc[e] + bsel[e]; mx = fmaxf(mx, w[e]); }
        float s = 0.f;
#pragma unroll
        for (int e = 0; e < NE; e++) { w[e] = expf(w[e] - mx); s += w[e]; }
        float inv = 1.f / s;
#pragma unroll
        for (int e = 0; e < NE; e++) w[e] *= inv;

        int ord[NE]; bool used[NE];
#pragma unroll
        for (int e = 0; e < NE; e++) used[e] = false;
#pragma unroll
        for (int j = 0; j < NE; j++) {
            int best = -1; float bv = -1e30f;
#pragma unroll
            for (int e = 0; e < NE; e++)
                if (!used[e] && w[e] > bv) { bv = w[e]; best = e; }
            ord[j] = best; used[best] = true;
        }
        float sws[NE]; float cum = 0.f;
#pragma unroll
        for (int j = 0; j < NE; j++) {
            float tw = w[ord[j]];
            cum += tw;
            sws[j] = fmaxf(fminf(cum, CAP) - cum + tw, 0.f);
        }
#pragma unroll
        for (int e = 0; e < NE; e++) {
            float wt = sws[ord[e]];   // faithful take_along_axis(sw_sorted, order)
            if (wt > 0.f) {
                int pos = atomicAdd(&g_count[e], 1);
                g_list[e * N_TOK + pos] = n;
                g_wt [e * N_TOK + pos] = wt;
            }
        }
    }
}

// ---------------- prep: convert x -> fp16 ----------------
__global__ void convert_x_kernel(const float* __restrict__ x) {
    size_t i = (size_t)blockIdx.x * blockDim.x + threadIdx.x;
    float4 v = reinterpret_cast<const float4*>(x)[i];
    __half h[4];
    h[0] = __float2half(v.x); h[1] = __float2half(v.y);
    h[2] = __float2half(v.z); h[3] = __float2half(v.w);
    *reinterpret_cast<uint2*>(&g_xh[i * 4]) = *reinterpret_cast<uint2*>(h);
}

// ---------------- prep: transpose W -> [e][n][k] fp16 ----------------
template<int WHICH>
__global__ void transpose_kernel(const float* __restrict__ W) {
    __half* Th = (WHICH == 1) ? g_w1h : g_w2h;
    int e  = blockIdx.z;
    int k0 = blockIdx.x * 32;
    int n0 = blockIdx.y * 32;
    __shared__ float t[32][33];
    int tx = threadIdx.x, ty = threadIdx.y;   // (32,8)
    const float* src = W + ((size_t)e * DMODEL + k0) * DMODEL + n0;
#pragma unroll
    for (int j = 0; j < 4; j++)
        t[ty + 8 * j][tx] = src[(size_t)(ty + 8 * j) * DMODEL + tx];
    __syncthreads();
    size_t obase = (size_t)e * DMODEL * DMODEL;
#pragma unroll
    for (int j = 0; j < 4; j++) {
        float v = t[tx][ty + 8 * j];
        size_t o = obase + (size_t)(n0 + ty + 8 * j) * DMODEL + k0 + tx;
        Th[o] = __float2half(v);
    }
}

// ---------------- HMMA expert GEMM ----------------
// 128x64 CTA tile, 4 warps (2 M x 2 N), 64x32 per warp, single fp16 A & B.
// Stage: A(8K) + B(4K) = 12KB; 4 stages = 48KB smem -> 4 CTAs/SM.
#define A_TILE_B 8192
#define B_TILE_B 4096
#define STAGE_BYTES (A_TILE_B + B_TILE_B)  // 12KB
#define SMEM_BYTES  (STAGES * STAGE_BYTES) // 48KB

template<int PHASE>
__global__ __launch_bounds__(128, 4)
void moe_gemm(const float* __restrict__ bias, float* __restrict__ out) {
    int e = blockIdx.z;
    int cnt = g_count[e];
    int row0 = blockIdx.x * TM;
    if (row0 >= cnt) return;
    int n0 = blockIdx.y * TN;

    extern __shared__ char smem[];
    uint32_t sbase = smem_u32(smem);

    int tid = threadIdx.x, wid = tid >> 5, lane = tid & 31;

    // ---- loader setup: 128 threads; seg=tid&3 (16B), r0l=tid>>2 (0..31)
    // A rows: r0l + 32q (q<4); B rows: r0l + 32q (q<2)
    int seg = tid & 3;
    int r0l = tid >> 2;
    const __half *ahr[4], *bhr[2];
    uint32_t sts_a[4], sts_b[2];
#pragma unroll
    for (int q = 0; q < 4; q++) {
        int rl = r0l + 32 * q;         // 0..127
        int r = row0 + rl; if (r > cnt - 1) r = cnt - 1;
        if (PHASE == 1) {
            ahr[q] = g_xh + (size_t)g_list[e * N_TOK + r] * DMODEL;
        } else {
            ahr[q] = g_h + ((size_t)e * N_TOK + r) * DMODEL;
        }
        sts_a[q] = sw64((uint32_t)rl * 64 + seg * 16);
    }
#pragma unroll
    for (int q = 0; q < 2; q++) {
        int rl = r0l + 32 * q;         // 0..63
        size_t brow = ((size_t)e * DMODEL + (n0 + rl)) * DMODEL;
        bhr[q] = ((PHASE == 1) ? g_w1h : g_w2h) + brow;
        sts_b[q] = sw64((uint32_t)rl * 64 + seg * 16);
    }

    auto load_stage = [&](int s, int c) {
        uint32_t st = sbase + s * STAGE_BYTES;
        int k0 = c * KC + seg * 8;
#pragma unroll
        for (int q = 0; q < 4; q++)
            CP16(st + sts_a[q], (const void*)(ahr[q] + k0));
#pragma unroll
        for (int q = 0; q < 2; q++)
            CP16(st + A_TILE_B + sts_b[q], (const void*)(bhr[q] + k0));
    };

    // ---- compute setup ----
    int warpM = wid & 1;       // 0..1
    int warpN = wid >> 1;      // 0..1
    int a_row = (lane & 15);
    int kchunk16 = (lane >> 4) * 16;     // 0 or 16 bytes
    int b_row = (lane & 7) + ((lane >> 3) & 1) * 8;

    uint32_t arowb[4], browb[2];
#pragma unroll
    for (int mt = 0; mt < 4; mt++)
        arowb[mt] = (uint32_t)(warpM * 64 + mt * 16 + a_row) * 64;
#pragma unroll
    for (int g = 0; g < 2; g++)
        browb[g] = (uint32_t)(warpN * 32 + g * 16 + b_row) * 64;

    float acc[4][4][4];
#pragma unroll
    for (int mt = 0; mt < 4; mt++)
#pragma unroll
        for (int j = 0; j < 4; j++)
#pragma unroll
            for (int q = 0; q < 4; q++) acc[mt][j][q] = 0.f;

    // ---- pipeline: 4 stages, depth-3 prologue, 1 barrier per chunk ----
    load_stage(0, 0); CP_COMMIT();
    load_stage(1, 1); CP_COMMIT();
    load_stage(2, 2); CP_COMMIT();

    int s = 0;
    for (int c = 0; c < NCHUNK; ++c) {
        CP_WAIT2();
        __syncthreads();

        uint32_t st = sbase + s * STAGE_BYTES;
        uint32_t sA = st, sB = st + A_TILE_B;

#pragma unroll
        for (int k16 = 0; k16 < KC / 16; ++k16) {
            uint32_t koff = (uint32_t)k16 * 32 + kchunk16;
            uint32_t bf[2][4];
#pragma unroll
            for (int g = 0; g < 2; g++) {
                uint32_t so = sw64(browb[g] + koff);
                ldsm4(bf[g], sB + so);
            }
#pragma unroll
            for (int mt = 0; mt < 4; mt++) {
                uint32_t af[4];
                uint32_t so = sw64(arowb[mt] + koff);
                ldsm4(af, sA + so);
#pragma unroll
                for (int j = 0; j < 4; j++) {
                    int g = j >> 1, sub = j & 1;
                    mma16816(acc[mt][j], af, bf[g][0 + sub], bf[g][2 + sub]);
                }
            }
        }
        if (c + 3 < NCHUNK) load_stage((c + 3) % STAGES, c + 3);
        CP_COMMIT();
        if (++s == STAGES) s = 0;
    }

    // ---- epilogue ----
    int mrow_base = row0 + warpM * 64 + (lane >> 2);
    int ncol_base = n0 + warpN * 32 + (lane & 3) * 2;

    if (PHASE == 1) {
#pragma unroll
        for (int mt = 0; mt < 4; mt++) {
#pragma unroll
            for (int half = 0; half < 2; half++) {
                int r = mrow_base + mt * 16 + half * 8;
                if (r >= cnt) continue;
                size_t hb = ((size_t)e * N_TOK + r) * DMODEL;
#pragma unroll
                for (int j = 0; j < 4; j++) {
                    int ncol = ncol_base + j * 8;
                    float v0 = acc[mt][j][half * 2 + 0] + bias[e * DMODEL + ncol];
                    float v1 = acc[mt][j][half * 2 + 1] + bias[e * DMODEL + ncol + 1];
                    v0 = fmaxf(v0, 0.f); v1 = fmaxf(v1, 0.f);
                    __half2 hp;
                    hp.x = __float2half(v0); hp.y = __float2half(v1);
                    *reinterpret_cast<__half2*>(&g_h[hb + ncol]) = hp;
                }
            }
        }
    } else {
#pragma unroll
        for (int mt = 0; mt < 4; mt++) {
#pragma unroll
            for (int half = 0; half < 2; half++) {
                int r = mrow_base + mt * 16 + half * 8;
                if (r >= cnt) continue;
                int tok = g_list[e * N_TOK + r];
                float wt = g_wt[e * N_TOK + r];
                float* orow = out + (size_t)tok * DMODEL;
#pragma unroll
                for (int j = 0; j < 4; j++) {
                    int ncol = ncol_base + j * 8;
                    float y0 = acc[mt][j][half * 2 + 0] + bias[e * DMODEL + ncol];
                    float y1 = acc[mt][j][half * 2 + 1] + bias[e * DMODEL + ncol + 1];
                    atomicAdd(orow + ncol,     wt * y0);
                    atomicAdd(orow + ncol + 1, wt * y1);
                }
            }
        }
    }
}

// ---------------- launch ----------------
extern "C" void kernel_launch(void* const* d_in, const int* in_sizes, int n_in,
                              void* d_out, int out_size) {
    const float* x    = (const float*)d_in[0];
    const float* Wsel = (const float*)d_in[1];
    const float* bsel = (const float*)d_in[2];
    const float* W1   = (const float*)d_in[3];
    const float* b1   = (const float*)d_in[4];
    const float* W2   = (const float*)d_in[5];
    const float* b2   = (const float*)d_in[6];
    float* out = (float*)d_out;

    cudaFuncSetAttribute(moe_gemm<1>, cudaFuncAttributeMaxDynamicSharedMemorySize, SMEM_BYTES);
    cudaFuncSetAttribute(moe_gemm<2>, cudaFuncAttributeMaxDynamicSharedMemorySize, SMEM_BYTES);

    cudaMemsetAsync(out, 0, (size_t)out_size * sizeof(float));
    zero_counts_kernel<<<1, 32>>>();
    router_kernel<<<N_TOK / 8, 256>>>(x, Wsel, bsel);

    convert_x_kernel<<<(N_TOK * DMODEL / 4) / 256, 256>>>(x);
    {
        dim3 g(32, 32, NE), b(32, 8);
        transpose_kernel<1><<<g, b>>>(W1);
        transpose_kernel<2><<<g, b>>>(W2);
    }

    dim3 gg(N_TOK / TM, DMODEL / TN, NE);
    moe_gemm<1><<<gg, 128, SMEM_BYTES>>>(b1, nullptr);
    moe_gemm<2><<<gg, 128, SMEM_BYTES>>>(b2, out);
}